// round 12
// baseline (speedup 1.0000x reference)
#include <cuda_runtime.h>
#include <cuda_bf16.h>
#include <cstdint>

// Fixed problem shape (SoftAggBasic): x [B,N,D] f32, ix [N], S segments.
constexpr int B = 8;
constexpr int N = 65536;
constexpr int D = 512;
constexpr int S = 1024;
constexpr int PREP_CTAS = 4;
constexpr int ITEMS = N / (PREP_CTAS * 1024);  // 16

// HMMA GEMM tiling: z[8192,512] = X[8192,512] @ W[512,512]^T(n,k)
constexpr int KT = 32;              // K per SMEM stage
constexpr int NSTG = D / KT;        // 16 stages
constexpr int ROWB = 80;            // padded smem row: 32 bf16 = 64B + 16B pad
constexpr int A_SZ = 128 * ROWB;    // 10240 B per 128-row tile
constexpr int STG_AH = 0;
constexpr int STG_AL = A_SZ;
constexpr int STG_BH = 2 * A_SZ;
constexpr int STG_BL = 3 * A_SZ;
constexpr int STAGE = 4 * A_SZ;     // 40960 B
constexpr int NSB = 3;              // cp.async ring depth
constexpr int SMEM_TOTAL = NSB * STAGE;  // 122880 B (>= 64KB z tile alias)

// ---------------- device scratch (no allocations allowed) ----------------
__device__ int   g_ix[N];
__device__ int   g_hist4[PREP_CTAS][S];
__device__ int   g_offs[S + 1];
__device__ int   g_cursor[S];
__device__ int   g_perm[N];
__device__ __nv_bfloat16 g_xh[(size_t)B * S * D];   // xbar hi (8 MB)
__device__ __nv_bfloat16 g_xl[(size_t)B * S * D];   // xbar lo (8 MB)
__device__ __nv_bfloat16 g_WTh[(size_t)D * D];      // (Wf@Wh)^T hi  [n,k]
__device__ __nv_bfloat16 g_WTl[(size_t)D * D];      // (Wf@Wh)^T lo
__device__ float g_bc[D];                           // bf @ Wh + bh

// ---------------- helpers ----------------
__device__ __forceinline__ uint32_t smem_u32(const void* p) {
    uint32_t a;
    asm("{ .reg .u64 t; cvta.to.shared.u64 t, %1; cvt.u32.u64 %0, t; }"
        : "=r"(a) : "l"(p));
    return a;
}

__device__ __forceinline__ void cpa16(uint32_t dst, const void* src) {
    asm volatile("cp.async.cg.shared.global [%0], [%1], 16;"
                 :: "r"(dst), "l"(src) : "memory");
}
__device__ __forceinline__ void cpa_commit() {
    asm volatile("cp.async.commit_group;" ::: "memory");
}
template <int NW>
__device__ __forceinline__ void cpa_wait() {
    asm volatile("cp.async.wait_group %0;" :: "n"(NW) : "memory");
}

// split f32 -> bf16 hi/lo
__device__ __forceinline__ void bsplit(float v, unsigned short& h,
                                       unsigned short& l) {
    __nv_bfloat16 hb = __float2bfloat16_rn(v);
    __nv_bfloat16 lb = __float2bfloat16_rn(v - __bfloat162float(hb));
    h = __bfloat16_as_ushort(hb);
    l = __bfloat16_as_ushort(lb);
}

__device__ __forceinline__ void ldsm4(uint32_t& f0, uint32_t& f1, uint32_t& f2,
                                      uint32_t& f3, uint32_t addr) {
    asm volatile(
        "ldmatrix.sync.aligned.m8n8.x4.shared.b16 {%0,%1,%2,%3}, [%4];"
        : "=r"(f0), "=r"(f1), "=r"(f2), "=r"(f3) : "r"(addr));
}

__device__ __forceinline__ void hmma(float* d, const uint32_t* a,
                                     const uint32_t* b) {
    asm volatile(
        "mma.sync.aligned.m16n8k16.row.col.f32.bf16.bf16.f32 "
        "{%0,%1,%2,%3}, {%4,%5,%6,%7}, {%8,%9}, {%0,%1,%2,%3};"
        : "+f"(d[0]), "+f"(d[1]), "+f"(d[2]), "+f"(d[3])
        : "r"(a[0]), "r"(a[1]), "r"(a[2]), "r"(a[3]), "r"(b[0]), "r"(b[1]));
}

// ---------------- prep 1: ix normalize + per-CTA histogram ----------------
// int64/int32 autodetect: little-endian int64 in [0,1024) => odd words zero.
__global__ __launch_bounds__(1024) void k_prep1(const int* __restrict__ raw) {
    __shared__ int hist[S];
    int t = threadIdx.x, c = blockIdx.x;
    hist[t] = 0;
    int any = 0;
#pragma unroll
    for (int i = 0; i < 16; i++) any |= raw[2 * i + 1];
    __syncthreads();
    int base = c * (ITEMS * 1024);
#pragma unroll
    for (int i = 0; i < ITEMS; i++) {
        int n = base + i * 1024 + t;
        int v = (any == 0) ? raw[2 * n] : raw[n];
        g_ix[n] = v;
        atomicAdd(&hist[v], 1);
    }
    __syncthreads();
    g_hist4[c][t] = hist[t];
}

// single block, S=1024 threads, warp-shfl hierarchical scan
__global__ void k_scan() {
    __shared__ int ws[32];
    int t = threadIdx.x, lane = t & 31, w = t >> 5;
    int c = 0;
#pragma unroll
    for (int j = 0; j < PREP_CTAS; j++) c += g_hist4[j][t];
    int v = c;
#pragma unroll
    for (int off = 1; off < 32; off <<= 1) {
        int u = __shfl_up_sync(~0u, v, off);
        if (lane >= off) v += u;
    }
    if (lane == 31) ws[w] = v;
    __syncthreads();
    if (w == 0) {
        int s2 = ws[lane];
#pragma unroll
        for (int off = 1; off < 32; off <<= 1) {
            int u = __shfl_up_sync(~0u, s2, off);
            if (lane >= off) s2 += u;
        }
        ws[lane] = s2;
    }
    __syncthreads();
    int incl = v + (w ? ws[w - 1] : 0);
    g_offs[t + 1] = incl;
    if (t == 0) g_offs[0] = 0;
    g_cursor[t] = incl - c;
}

// ---------------- prep 2: scatter with smem-aggregated reservation -------
__global__ __launch_bounds__(1024) void k_prep2() {
    __shared__ int hist[S];
    __shared__ int basearr[S];
    int t = threadIdx.x, c = blockIdx.x;
    hist[t] = 0;
    __syncthreads();
    int base = c * (ITEMS * 1024);
    int lp[ITEMS], sv[ITEMS];
#pragma unroll
    for (int i = 0; i < ITEMS; i++) {
        int n = base + i * 1024 + t;
        int s = g_ix[n];
        sv[i] = s;
        lp[i] = atomicAdd(&hist[s], 1);
    }
    __syncthreads();
    basearr[t] = atomicAdd(&g_cursor[t], hist[t]);
    __syncthreads();
#pragma unroll
    for (int i = 0; i < ITEMS; i++)
        g_perm[basearr[sv[i]] + lp[i]] = base + i * 1024 + t;
}

// ---------------- pass 1: fused logits + softmax + weighted segment mean ---
// Warp per (b, segment); epilogue writes xbar as bf16 hi/lo split.
__global__ __launch_bounds__(256) void k_pass1(const float4* __restrict__ x4,
                                               const float4* __restrict__ Wg4,
                                               const float* __restrict__ bg) {
    int wid = threadIdx.x >> 5, lane = threadIdx.x & 31;
    int pair = blockIdx.x * 8 + wid;   // = b*S + s
    int b = pair >> 10;
    int s = pair & (S - 1);

    float4 wgv[4];
#pragma unroll
    for (int j = 0; j < 4; j++) wgv[j] = Wg4[lane + 32 * j];
    float bg0 = bg[0];

    int start = g_offs[s], end = g_offs[s + 1];
    const float4* xb = x4 + (size_t)b * N * (D / 4);

    float4 acc[4];
#pragma unroll
    for (int j = 0; j < 4; j++) acc[j] = make_float4(0.f, 0.f, 0.f, 0.f);
    float denom = 0.f;

    for (int r = start; r < end; r += 2) {
        int n0 = g_perm[r];
        int n1 = (r + 1 < end) ? g_perm[r + 1] : n0;
        const float4* p0 = xb + (size_t)n0 * (D / 4);
        const float4* p1 = xb + (size_t)n1 * (D / 4);
        float4 xv0[4], xv1[4];
#pragma unroll
        for (int j = 0; j < 4; j++) xv0[j] = p0[lane + 32 * j];
#pragma unroll
        for (int j = 0; j < 4; j++) xv1[j] = p1[lane + 32 * j];

        float d0 = 0.f, d1 = 0.f;
#pragma unroll
        for (int j = 0; j < 4; j++) {
            d0 += xv0[j].x * wgv[j].x + xv0[j].y * wgv[j].y +
                  xv0[j].z * wgv[j].z + xv0[j].w * wgv[j].w;
            d1 += xv1[j].x * wgv[j].x + xv1[j].y * wgv[j].y +
                  xv1[j].z * wgv[j].z + xv1[j].w * wgv[j].w;
        }
#pragma unroll
        for (int off = 16; off; off >>= 1) {
            d0 += __shfl_xor_sync(~0u, d0, off);
            d1 += __shfl_xor_sync(~0u, d1, off);
        }
        float e0 = expf(d0 + bg0);
        float e1 = (r + 1 < end) ? expf(d1 + bg0) : 0.f;
        denom += e0 + e1;
#pragma unroll
        for (int j = 0; j < 4; j++) {
            acc[j].x += e0 * xv0[j].x + e1 * xv1[j].x;
            acc[j].y += e0 * xv0[j].y + e1 * xv1[j].y;
            acc[j].z += e0 * xv0[j].z + e1 * xv1[j].z;
            acc[j].w += e0 * xv0[j].w + e1 * xv1[j].w;
        }
    }
    float inv = (denom > 0.f) ? 1.f / denom : 0.f;
#pragma unroll
    for (int j = 0; j < 4; j++) {
        float v0 = acc[j].x * inv, v1 = acc[j].y * inv;
        float v2 = acc[j].z * inv, v3 = acc[j].w * inv;
        unsigned short h0, h1, h2, h3, l0, l1, l2, l3;
        bsplit(v0, h0, l0);
        bsplit(v1, h1, l1);
        bsplit(v2, h2, l2);
        bsplit(v3, h3, l3);
        size_t off = (size_t)pair * D + 4 * (lane + 32 * j);
        uint2 uh, ul;
        uh.x = (uint32_t)h0 | ((uint32_t)h1 << 16);
        uh.y = (uint32_t)h2 | ((uint32_t)h3 << 16);
        ul.x = (uint32_t)l0 | ((uint32_t)l1 << 16);
        ul.y = (uint32_t)l2 | ((uint32_t)l3 << 16);
        *(uint2*)(g_xh + off) = uh;
        *(uint2*)(g_xl + off) = ul;
    }
}

// ---------------- fold weights: WcT = (Wf @ Wh)^T as bf16 hi/lo -----------
__global__ void k_bc(const float* __restrict__ Wh, const float* __restrict__ bf,
                     const float* __restrict__ bh) {
    int d = blockIdx.x * blockDim.x + threadIdx.x;
    float acc = bh[d];
    for (int k = 0; k < D; k++) acc += bf[k] * Wh[(size_t)k * D + d];
    g_bc[d] = acc;
}

__global__ __launch_bounds__(256) void k_wc(const float* __restrict__ Wf,
                                            const float* __restrict__ Wh) {
    __shared__ float Af[32][33], Bf[32][33];
    int t = threadIdx.x;
    int row0 = blockIdx.y * 32, col0 = blockIdx.x * 32;
    int c = t & 31, g = t >> 5;
    float acc[4] = {0.f, 0.f, 0.f, 0.f};
    for (int k0 = 0; k0 < D; k0 += 32) {
#pragma unroll
        for (int i = 0; i < 4; i++) {
            int idx = t + i * 256;
            int r = idx >> 5, cc = idx & 31;
            Af[r][cc] = Wf[(size_t)(row0 + r) * D + k0 + cc];
            Bf[r][cc] = Wh[(size_t)(k0 + r) * D + col0 + cc];
        }
        __syncthreads();
#pragma unroll
        for (int k = 0; k < 32; k++) {
            float bv = Bf[k][c];
#pragma unroll
            for (int i = 0; i < 4; i++) acc[i] += Af[g * 4 + i][k] * bv;
        }
        __syncthreads();
    }
    // transpose on write: WT[n][k] = Wc[k][n], split bf16 hi/lo
#pragma unroll
    for (int i = 0; i < 4; i++) {
        unsigned short h, l;
        bsplit(acc[i], h, l);
        size_t o = (size_t)(col0 + c) * D + row0 + g * 4 + i;
        g_WTh[o] = __ushort_as_bfloat16(h);
        g_WTl[o] = __ushort_as_bfloat16(l);
    }
}

// ---------------- fused HMMA GEMM + segment-expansion write ---------------
// CTA tile 128x128, 256 threads = 8 warps as 2(M)x4(N).
// Phase 1: z tile = X @ WT^T + bc via bf16 hi/lo 3-term HMMA, 3-stage
//          cp.async ring, one sync per stage.
// Phase 2: stage z tile (128x128 f32 = 64KB) in SMEM (aliases ring buffers),
//          then expand: out[b*N + perm[r], n0:n0+128] = ztile[row], streamed.
// This removes the z gmem round-trip and the separate gather kernel.
__global__ __launch_bounds__(256) void k_tgz(float4* __restrict__ out4) {
    extern __shared__ char sm[];
    uint32_t sb = smem_u32(sm);
    int t = threadIdx.x;
    int lane = t & 31, wid = t >> 5;
    int m0 = blockIdx.x * 128, n0 = blockIdx.y * 128;
    int wm = (wid & 1) * 64;   // warp M offset in tile
    int wn = (wid >> 1) * 32;  // warp N offset in tile

    // loader role: thread t covers row t>>1, half (t&1) (16 bf16 = 32 B)
    int lrow = t >> 1, half = t & 1;
    const uint4* gah = (const uint4*)(g_xh + (size_t)(m0 + lrow) * D) + half * 2;
    const uint4* gal = (const uint4*)(g_xl + (size_t)(m0 + lrow) * D) + half * 2;
    const uint4* gbh = (const uint4*)(g_WTh + (size_t)(n0 + lrow) * D) + half * 2;
    const uint4* gbl = (const uint4*)(g_WTl + (size_t)(n0 + lrow) * D) + half * 2;
    uint32_t sto = (uint32_t)lrow * ROWB + half * 32;

    float d[4][4][4];
#pragma unroll
    for (int mi = 0; mi < 4; mi++)
#pragma unroll
        for (int nj = 0; nj < 4; nj++)
#pragma unroll
            for (int q = 0; q < 4; q++) d[mi][nj][q] = 0.f;

    auto load_stage = [&](int s) {
        uint32_t bp = sb + (uint32_t)(s % NSB) * STAGE;
        int ko = s * 4;  // 4 uint4 per 32-elem k chunk (2 per half)
        cpa16(bp + STG_AH + sto, gah + ko);
        cpa16(bp + STG_AH + sto + 16, gah + ko + 1);
        cpa16(bp + STG_AL + sto, gal + ko);
        cpa16(bp + STG_AL + sto + 16, gal + ko + 1);
        cpa16(bp + STG_BH + sto, gbh + ko);
        cpa16(bp + STG_BH + sto + 16, gbh + ko + 1);
        cpa16(bp + STG_BL + sto, gbl + ko);
        cpa16(bp + STG_BL + sto + 16, gbl + ko + 1);
        cpa_commit();
    };

    load_stage(0);
    load_stage(1);

    // ldmatrix per-lane offsets (validated round-8 mapping)
    int r8 = lane & 7, grp = lane >> 3;
    uint32_t a_off = (uint32_t)(((grp & 1) * 8 + r8) * ROWB + ((grp >> 1) * 8) * 2);
    uint32_t b_off = (uint32_t)((((grp >> 1) * 8) + r8) * ROWB + ((grp & 1) * 8) * 2);

    for (int s = 0; s < NSTG; s++) {
        if (s < NSTG - 1) cpa_wait<1>(); else cpa_wait<0>();
        __syncthreads();  // stage s visible to all; ring slot (s+2)%NSB free
        if (s + 2 < NSTG) load_stage(s + 2);

        uint32_t bb = sb + (uint32_t)(s % NSB) * STAGE;
#pragma unroll
        for (int kk = 0; kk < KT; kk += 16) {
            uint32_t bH[4][2], bL[4][2];
#pragma unroll
            for (int ni = 0; ni < 2; ni++) {
                uint32_t bd = bb + (uint32_t)((wn + ni * 16) * ROWB + kk * 2) + b_off;
                ldsm4(bH[2 * ni][0], bH[2 * ni][1], bH[2 * ni + 1][0],
                      bH[2 * ni + 1][1], bd + STG_BH);
                ldsm4(bL[2 * ni][0], bL[2 * ni][1], bL[2 * ni + 1][0],
                      bL[2 * ni + 1][1], bd + STG_BL);
            }
#pragma unroll
            for (int mi = 0; mi < 4; mi++) {
                uint32_t aH[4], aL[4];
                uint32_t ad = bb + (uint32_t)((wm + mi * 16) * ROWB + kk * 2) + a_off;
                ldsm4(aH[0], aH[1], aH[2], aH[3], ad + STG_AH);
                ldsm4(aL[0], aL[1], aL[2], aL[3], ad + STG_AL);
#pragma unroll
                for (int nj = 0; nj < 4; nj++) {
                    hmma(d[mi][nj], aH, bH[nj]);
                    hmma(d[mi][nj], aH, bL[nj]);
                    hmma(d[mi][nj], aL, bH[nj]);
                }
            }
        }
    }
    __syncthreads();  // compute done; ring buffers now reusable as z tile

    // Phase 2a: stage z tile (+bias) into SMEM. zs[row][col], 128x128 f32.
    float* zs = (float*)sm;
    int fr = lane >> 2, fc = 2 * (lane & 3);
#pragma unroll
    for (int nj = 0; nj < 4; nj++) {
        int col = wn + nj * 8 + fc;
        float2 bb2 = *(const float2*)(g_bc + n0 + col);
#pragma unroll
        for (int mi = 0; mi < 4; mi++) {
            int row = wm + mi * 16 + fr;
            float2 o0, o1;
            o0.x = d[mi][nj][0] + bb2.x;
            o0.y = d[mi][nj][1] + bb2.y;
            o1.x = d[mi][nj][2] + bb2.x;
            o1.y = d[mi][nj][3] + bb2.y;
            *(float2*)(zs + (size_t)row * 128 + col) = o0;
            *(float2*)(zs + (size_t)(row + 8) * 128 + col) = o1;
        }
    }
    __syncthreads();

    // Phase 2b: segment expansion. Warp handles z rows wid, wid+8, ...
    // Lane l holds the row's float4 slot l in a register; inner loop is
    // one streaming STG.128 per output row.
    for (int i = wid; i < 128; i += 8) {
        int pair = m0 + i;
        int seg = pair & (S - 1);
        int b = pair >> 10;
        int st = g_offs[seg], en = g_offs[seg + 1];
        float4 v = *((const float4*)(zs + (size_t)i * 128) + lane);
        size_t obase = (size_t)b * N * 128 + (n0 >> 2) + lane;
        int r = st;
        for (; r + 4 <= en; r += 4) {
            int na = g_perm[r], nb2 = g_perm[r + 1];
            int nc = g_perm[r + 2], nd = g_perm[r + 3];
            __stcs(out4 + obase + (size_t)na * 128, v);
            __stcs(out4 + obase + (size_t)nb2 * 128, v);
            __stcs(out4 + obase + (size_t)nc * 128, v);
            __stcs(out4 + obase + (size_t)nd * 128, v);
        }
        for (; r < en; r++) {
            int n = g_perm[r];
            __stcs(out4 + obase + (size_t)n * 128, v);
        }
    }
}

// ---------------- launch ----------------
extern "C" void kernel_launch(void* const* d_in, const int* in_sizes, int n_in,
                              void* d_out, int out_size) {
    const float* x  = (const float*)d_in[0];
    const int*   ix = (const int*)d_in[1];
    const float* Wf = (const float*)d_in[2];
    const float* bf = (const float*)d_in[3];
    const float* Wg = (const float*)d_in[4];
    const float* bg = (const float*)d_in[5];
    const float* Wh = (const float*)d_in[6];
    const float* bh = (const float*)d_in[7];
    float* out = (float*)d_out;
    (void)in_sizes; (void)n_in; (void)out_size;

    cudaFuncSetAttribute(k_tgz, cudaFuncAttributeMaxDynamicSharedMemorySize,
                         SMEM_TOTAL);

    k_prep1<<<PREP_CTAS, 1024>>>(ix);
    k_scan<<<1, S>>>();
    k_prep2<<<PREP_CTAS, 1024>>>();
    k_pass1<<<(B * S) / 8, 256>>>((const float4*)x, (const float4*)Wg, bg);

    k_bc<<<D / 256, 256>>>(Wh, bf, bh);
    k_wc<<<dim3(D / 32, D / 32), 256>>>(Wf, Wh);

    k_tgz<<<dim3((B * S) / 128, D / 128), 256, SMEM_TOTAL>>>((float4*)out);
}

// round 13
// speedup vs baseline: 1.0118x; 1.0118x over previous
#include <cuda_runtime.h>
#include <cuda_bf16.h>
#include <cstdint>

// Fixed problem shape (SoftAggBasic): x [B,N,D] f32, ix [N], S segments.
constexpr int B = 8;
constexpr int N = 65536;
constexpr int D = 512;
constexpr int S = 1024;
constexpr int PREP_CTAS = 4;
constexpr int ITEMS = N / (PREP_CTAS * 1024);  // 16

// HMMA GEMM tiling: z[8192,512] = X[8192,512] @ W[512,512]^T(n,k)
constexpr int KT = 32;              // K per SMEM stage
constexpr int NSTG = D / KT;        // 16 stages
constexpr int ROWB = 80;            // padded smem row: 32 bf16 = 64B + 16B pad
constexpr int A_SZ = 128 * ROWB;    // 10240 B per 128-row tile
constexpr int STG_AH = 0;
constexpr int STG_AL = A_SZ;
constexpr int STG_BH = 2 * A_SZ;
constexpr int STG_BL = 3 * A_SZ;
constexpr int STAGE = 4 * A_SZ;     // 40960 B
constexpr int SMEM_TOTAL = 2 * STAGE;  // 81920 B (>= 64KB z tile alias)
                                       // 2 CTAs/SM co-resident

// ---------------- device scratch (no allocations allowed) ----------------
__device__ int   g_ix[N];
__device__ int   g_hist4[PREP_CTAS][S];
__device__ int   g_offs[S + 1];
__device__ int   g_cursor[S];
__device__ int   g_perm[N];
__device__ __nv_bfloat16 g_xh[(size_t)B * S * D];   // xbar hi (8 MB)
__device__ __nv_bfloat16 g_xl[(size_t)B * S * D];   // xbar lo (8 MB)
__device__ __nv_bfloat16 g_WTh[(size_t)D * D];      // (Wf@Wh)^T hi  [n,k]
__device__ __nv_bfloat16 g_WTl[(size_t)D * D];      // (Wf@Wh)^T lo
__device__ float g_bc[D];                           // bf @ Wh + bh

// ---------------- helpers ----------------
__device__ __forceinline__ uint32_t smem_u32(const void* p) {
    uint32_t a;
    asm("{ .reg .u64 t; cvta.to.shared.u64 t, %1; cvt.u32.u64 %0, t; }"
        : "=r"(a) : "l"(p));
    return a;
}

__device__ __forceinline__ void cpa16(uint32_t dst, const void* src) {
    asm volatile("cp.async.cg.shared.global [%0], [%1], 16;"
                 :: "r"(dst), "l"(src) : "memory");
}
__device__ __forceinline__ void cpa_commit() {
    asm volatile("cp.async.commit_group;" ::: "memory");
}
template <int NW>
__device__ __forceinline__ void cpa_wait() {
    asm volatile("cp.async.wait_group %0;" :: "n"(NW) : "memory");
}

// split f32 -> bf16 hi/lo
__device__ __forceinline__ void bsplit(float v, unsigned short& h,
                                       unsigned short& l) {
    __nv_bfloat16 hb = __float2bfloat16_rn(v);
    __nv_bfloat16 lb = __float2bfloat16_rn(v - __bfloat162float(hb));
    h = __bfloat16_as_ushort(hb);
    l = __bfloat16_as_ushort(lb);
}

__device__ __forceinline__ void ldsm4(uint32_t& f0, uint32_t& f1, uint32_t& f2,
                                      uint32_t& f3, uint32_t addr) {
    asm volatile(
        "ldmatrix.sync.aligned.m8n8.x4.shared.b16 {%0,%1,%2,%3}, [%4];"
        : "=r"(f0), "=r"(f1), "=r"(f2), "=r"(f3) : "r"(addr));
}

__device__ __forceinline__ void hmma(float* d, const uint32_t* a,
                                     const uint32_t* b) {
    asm volatile(
        "mma.sync.aligned.m16n8k16.row.col.f32.bf16.bf16.f32 "
        "{%0,%1,%2,%3}, {%4,%5,%6,%7}, {%8,%9}, {%0,%1,%2,%3};"
        : "+f"(d[0]), "+f"(d[1]), "+f"(d[2]), "+f"(d[3])
        : "r"(a[0]), "r"(a[1]), "r"(a[2]), "r"(a[3]), "r"(b[0]), "r"(b[1]));
}

// ---------------- prep 1: ix normalize + per-CTA histogram ----------------
// int64/int32 autodetect: little-endian int64 in [0,1024) => odd words zero.
__global__ __launch_bounds__(1024) void k_prep1(const int* __restrict__ raw) {
    __shared__ int hist[S];
    int t = threadIdx.x, c = blockIdx.x;
    hist[t] = 0;
    int any = 0;
#pragma unroll
    for (int i = 0; i < 16; i++) any |= raw[2 * i + 1];
    __syncthreads();
    int base = c * (ITEMS * 1024);
#pragma unroll
    for (int i = 0; i < ITEMS; i++) {
        int n = base + i * 1024 + t;
        int v = (any == 0) ? raw[2 * n] : raw[n];
        g_ix[n] = v;
        atomicAdd(&hist[v], 1);
    }
    __syncthreads();
    g_hist4[c][t] = hist[t];
}

// single block, S=1024 threads, warp-shfl hierarchical scan
__global__ void k_scan() {
    __shared__ int ws[32];
    int t = threadIdx.x, lane = t & 31, w = t >> 5;
    int c = 0;
#pragma unroll
    for (int j = 0; j < PREP_CTAS; j++) c += g_hist4[j][t];
    int v = c;
#pragma unroll
    for (int off = 1; off < 32; off <<= 1) {
        int u = __shfl_up_sync(~0u, v, off);
        if (lane >= off) v += u;
    }
    if (lane == 31) ws[w] = v;
    __syncthreads();
    if (w == 0) {
        int s2 = ws[lane];
#pragma unroll
        for (int off = 1; off < 32; off <<= 1) {
            int u = __shfl_up_sync(~0u, s2, off);
            if (lane >= off) s2 += u;
        }
        ws[lane] = s2;
    }
    __syncthreads();
    int incl = v + (w ? ws[w - 1] : 0);
    g_offs[t + 1] = incl;
    if (t == 0) g_offs[0] = 0;
    g_cursor[t] = incl - c;
}

// ---------------- prep 2: scatter with smem-aggregated reservation -------
__global__ __launch_bounds__(1024) void k_prep2() {
    __shared__ int hist[S];
    __shared__ int basearr[S];
    int t = threadIdx.x, c = blockIdx.x;
    hist[t] = 0;
    __syncthreads();
    int base = c * (ITEMS * 1024);
    int lp[ITEMS], sv[ITEMS];
#pragma unroll
    for (int i = 0; i < ITEMS; i++) {
        int n = base + i * 1024 + t;
        int s = g_ix[n];
        sv[i] = s;
        lp[i] = atomicAdd(&hist[s], 1);
    }
    __syncthreads();
    basearr[t] = atomicAdd(&g_cursor[t], hist[t]);
    __syncthreads();
#pragma unroll
    for (int i = 0; i < ITEMS; i++)
        g_perm[basearr[sv[i]] + lp[i]] = base + i * 1024 + t;
}

// ---------------- pass 1: fused logits + softmax + weighted segment mean ---
// Warp per (b, segment); epilogue writes xbar as bf16 hi/lo split.
__global__ __launch_bounds__(256) void k_pass1(const float4* __restrict__ x4,
                                               const float4* __restrict__ Wg4,
                                               const float* __restrict__ bg) {
    int wid = threadIdx.x >> 5, lane = threadIdx.x & 31;
    int pair = blockIdx.x * 8 + wid;   // = b*S + s
    int b = pair >> 10;
    int s = pair & (S - 1);

    float4 wgv[4];
#pragma unroll
    for (int j = 0; j < 4; j++) wgv[j] = Wg4[lane + 32 * j];
    float bg0 = bg[0];

    int start = g_offs[s], end = g_offs[s + 1];
    const float4* xb = x4 + (size_t)b * N * (D / 4);

    float4 acc[4];
#pragma unroll
    for (int j = 0; j < 4; j++) acc[j] = make_float4(0.f, 0.f, 0.f, 0.f);
    float denom = 0.f;

    for (int r = start; r < end; r += 2) {
        int n0 = g_perm[r];
        int n1 = (r + 1 < end) ? g_perm[r + 1] : n0;
        const float4* p0 = xb + (size_t)n0 * (D / 4);
        const float4* p1 = xb + (size_t)n1 * (D / 4);
        float4 xv0[4], xv1[4];
#pragma unroll
        for (int j = 0; j < 4; j++) xv0[j] = p0[lane + 32 * j];
#pragma unroll
        for (int j = 0; j < 4; j++) xv1[j] = p1[lane + 32 * j];

        float d0 = 0.f, d1 = 0.f;
#pragma unroll
        for (int j = 0; j < 4; j++) {
            d0 += xv0[j].x * wgv[j].x + xv0[j].y * wgv[j].y +
                  xv0[j].z * wgv[j].z + xv0[j].w * wgv[j].w;
            d1 += xv1[j].x * wgv[j].x + xv1[j].y * wgv[j].y +
                  xv1[j].z * wgv[j].z + xv1[j].w * wgv[j].w;
        }
#pragma unroll
        for (int off = 16; off; off >>= 1) {
            d0 += __shfl_xor_sync(~0u, d0, off);
            d1 += __shfl_xor_sync(~0u, d1, off);
        }
        float e0 = expf(d0 + bg0);
        float e1 = (r + 1 < end) ? expf(d1 + bg0) : 0.f;
        denom += e0 + e1;
#pragma unroll
        for (int j = 0; j < 4; j++) {
            acc[j].x += e0 * xv0[j].x + e1 * xv1[j].x;
            acc[j].y += e0 * xv0[j].y + e1 * xv1[j].y;
            acc[j].z += e0 * xv0[j].z + e1 * xv1[j].z;
            acc[j].w += e0 * xv0[j].w + e1 * xv1[j].w;
        }
    }
    float inv = (denom > 0.f) ? 1.f / denom : 0.f;
#pragma unroll
    for (int j = 0; j < 4; j++) {
        float v0 = acc[j].x * inv, v1 = acc[j].y * inv;
        float v2 = acc[j].z * inv, v3 = acc[j].w * inv;
        unsigned short h0, h1, h2, h3, l0, l1, l2, l3;
        bsplit(v0, h0, l0);
        bsplit(v1, h1, l1);
        bsplit(v2, h2, l2);
        bsplit(v3, h3, l3);
        size_t off = (size_t)pair * D + 4 * (lane + 32 * j);
        uint2 uh, ul;
        uh.x = (uint32_t)h0 | ((uint32_t)h1 << 16);
        uh.y = (uint32_t)h2 | ((uint32_t)h3 << 16);
        ul.x = (uint32_t)l0 | ((uint32_t)l1 << 16);
        ul.y = (uint32_t)l2 | ((uint32_t)l3 << 16);
        *(uint2*)(g_xh + off) = uh;
        *(uint2*)(g_xl + off) = ul;
    }
}

// ---------------- fold weights: WcT = (Wf @ Wh)^T as bf16 hi/lo -----------
__global__ void k_bc(const float* __restrict__ Wh, const float* __restrict__ bf,
                     const float* __restrict__ bh) {
    int d = blockIdx.x * blockDim.x + threadIdx.x;
    float acc = bh[d];
    for (int k = 0; k < D; k++) acc += bf[k] * Wh[(size_t)k * D + d];
    g_bc[d] = acc;
}

__global__ __launch_bounds__(256) void k_wc(const float* __restrict__ Wf,
                                            const float* __restrict__ Wh) {
    __shared__ float Af[32][33], Bf[32][33];
    int t = threadIdx.x;
    int row0 = blockIdx.y * 32, col0 = blockIdx.x * 32;
    int c = t & 31, g = t >> 5;
    float acc[4] = {0.f, 0.f, 0.f, 0.f};
    for (int k0 = 0; k0 < D; k0 += 32) {
#pragma unroll
        for (int i = 0; i < 4; i++) {
            int idx = t + i * 256;
            int r = idx >> 5, cc = idx & 31;
            Af[r][cc] = Wf[(size_t)(row0 + r) * D + k0 + cc];
            Bf[r][cc] = Wh[(size_t)(k0 + r) * D + col0 + cc];
        }
        __syncthreads();
#pragma unroll
        for (int k = 0; k < 32; k++) {
            float bv = Bf[k][c];
#pragma unroll
            for (int i = 0; i < 4; i++) acc[i] += Af[g * 4 + i][k] * bv;
        }
        __syncthreads();
    }
    // transpose on write: WT[n][k] = Wc[k][n], split bf16 hi/lo
#pragma unroll
    for (int i = 0; i < 4; i++) {
        unsigned short h, l;
        bsplit(acc[i], h, l);
        size_t o = (size_t)(col0 + c) * D + row0 + g * 4 + i;
        g_WTh[o] = __ushort_as_bfloat16(h);
        g_WTl[o] = __ushort_as_bfloat16(l);
    }
}

// ---------------- fused HMMA GEMM + segment-expansion write ---------------
// CTA tile 128x128, 256 threads = 8 warps as 2(M)x4(N).
// Phase 1: z tile = X @ WT^T + bc (bf16 hi/lo 3-term HMMA), double-buffered
//          cp.async (round-11-validated schedule).
// Phase 2: stage z tile (64KB, aliases ring buffers) then expand to out.
// __launch_bounds__(256,2): 2 CTAs/SM co-resident (81920B smem each), so one
// CTA's streaming-write phase overlaps the other CTA's HMMA phase.
__global__ __launch_bounds__(256, 2) void k_tgz(float4* __restrict__ out4) {
    extern __shared__ char sm[];
    uint32_t sb = smem_u32(sm);
    int t = threadIdx.x;
    int lane = t & 31, wid = t >> 5;
    int m0 = blockIdx.x * 128, n0 = blockIdx.y * 128;
    int wm = (wid & 1) * 64;   // warp M offset in tile
    int wn = (wid >> 1) * 32;  // warp N offset in tile

    // loader role: thread t covers row t>>1, half (t&1) (16 bf16 = 32 B)
    int lrow = t >> 1, half = t & 1;
    const uint4* gah = (const uint4*)(g_xh + (size_t)(m0 + lrow) * D) + half * 2;
    const uint4* gal = (const uint4*)(g_xl + (size_t)(m0 + lrow) * D) + half * 2;
    const uint4* gbh = (const uint4*)(g_WTh + (size_t)(n0 + lrow) * D) + half * 2;
    const uint4* gbl = (const uint4*)(g_WTl + (size_t)(n0 + lrow) * D) + half * 2;
    uint32_t sto = (uint32_t)lrow * ROWB + half * 32;

    float d[4][4][4];
#pragma unroll
    for (int mi = 0; mi < 4; mi++)
#pragma unroll
        for (int nj = 0; nj < 4; nj++)
#pragma unroll
            for (int q = 0; q < 4; q++) d[mi][nj][q] = 0.f;

    auto load_stage = [&](int s) {
        uint32_t bp = sb + (uint32_t)(s & 1) * STAGE;
        int ko = s * 4;  // 4 uint4 per 32-elem k chunk (2 per half)
        cpa16(bp + STG_AH + sto, gah + ko);
        cpa16(bp + STG_AH + sto + 16, gah + ko + 1);
        cpa16(bp + STG_AL + sto, gal + ko);
        cpa16(bp + STG_AL + sto + 16, gal + ko + 1);
        cpa16(bp + STG_BH + sto, gbh + ko);
        cpa16(bp + STG_BH + sto + 16, gbh + ko + 1);
        cpa16(bp + STG_BL + sto, gbl + ko);
        cpa16(bp + STG_BL + sto + 16, gbl + ko + 1);
        cpa_commit();
    };

    load_stage(0);

    // ldmatrix per-lane offsets (validated round-8 mapping)
    int r8 = lane & 7, grp = lane >> 3;
    uint32_t a_off = (uint32_t)(((grp & 1) * 8 + r8) * ROWB + ((grp >> 1) * 8) * 2);
    uint32_t b_off = (uint32_t)((((grp >> 1) * 8) + r8) * ROWB + ((grp & 1) * 8) * 2);

    for (int s = 0; s < NSTG; s++) {
        if (s < NSTG - 1) load_stage(s + 1);
        if (s < NSTG - 1) cpa_wait<1>(); else cpa_wait<0>();
        __syncthreads();  // stage s resident for all warps

        uint32_t bb = sb + (uint32_t)(s & 1) * STAGE;
#pragma unroll
        for (int kk = 0; kk < KT; kk += 16) {
            uint32_t bH[4][2], bL[4][2];
#pragma unroll
            for (int ni = 0; ni < 2; ni++) {
                uint32_t bd = bb + (uint32_t)((wn + ni * 16) * ROWB + kk * 2) + b_off;
                ldsm4(bH[2 * ni][0], bH[2 * ni][1], bH[2 * ni + 1][0],
                      bH[2 * ni + 1][1], bd + STG_BH);
                ldsm4(bL[2 * ni][0], bL[2 * ni][1], bL[2 * ni + 1][0],
                      bL[2 * ni + 1][1], bd + STG_BL);
            }
#pragma unroll
            for (int mi = 0; mi < 4; mi++) {
                uint32_t aH[4], aL[4];
                uint32_t ad = bb + (uint32_t)((wm + mi * 16) * ROWB + kk * 2) + a_off;
                ldsm4(aH[0], aH[1], aH[2], aH[3], ad + STG_AH);
                ldsm4(aL[0], aL[1], aL[2], aL[3], ad + STG_AL);
#pragma unroll
                for (int nj = 0; nj < 4; nj++) {
                    hmma(d[mi][nj], aH, bH[nj]);
                    hmma(d[mi][nj], aH, bL[nj]);
                    hmma(d[mi][nj], aL, bH[nj]);
                }
            }
        }
        __syncthreads();  // all warps done with stage s before it is reloaded
    }

    // Phase 2a: stage z tile (+bias) into SMEM. zs[row][col], 128x128 f32.
    float* zs = (float*)sm;
    int fr = lane >> 2, fc = 2 * (lane & 3);
#pragma unroll
    for (int nj = 0; nj < 4; nj++) {
        int col = wn + nj * 8 + fc;
        float2 bb2 = *(const float2*)(g_bc + n0 + col);
#pragma unroll
        for (int mi = 0; mi < 4; mi++) {
            int row = wm + mi * 16 + fr;
            float2 o0, o1;
            o0.x = d[mi][nj][0] + bb2.x;
            o0.y = d[mi][nj][1] + bb2.y;
            o1.x = d[mi][nj][2] + bb2.x;
            o1.y = d[mi][nj][3] + bb2.y;
            *(float2*)(zs + (size_t)row * 128 + col) = o0;
            *(float2*)(zs + (size_t)(row + 8) * 128 + col) = o1;
        }
    }
    __syncthreads();

    // Phase 2b: segment expansion. Warp handles z rows wid, wid+8, ...
    // Lane l holds the row's float4 slot l in a register; inner loop is
    // one streaming STG.128 per output row.
    for (int i = wid; i < 128; i += 8) {
        int pair = m0 + i;
        int seg = pair & (S - 1);
        int b = pair >> 10;
        int st = g_offs[seg], en = g_offs[seg + 1];
        float4 v = *((const float4*)(zs + (size_t)i * 128) + lane);
        size_t obase = (size_t)b * N * 128 + (n0 >> 2) + lane;
        int r = st;
        for (; r + 4 <= en; r += 4) {
            int na = g_perm[r], nb2 = g_perm[r + 1];
            int nc = g_perm[r + 2], nd = g_perm[r + 3];
            __stcs(out4 + obase + (size_t)na * 128, v);
            __stcs(out4 + obase + (size_t)nb2 * 128, v);
            __stcs(out4 + obase + (size_t)nc * 128, v);
            __stcs(out4 + obase + (size_t)nd * 128, v);
        }
        for (; r < en; r++) {
            int n = g_perm[r];
            __stcs(out4 + obase + (size_t)n * 128, v);
        }
    }
}

// ---------------- launch ----------------
extern "C" void kernel_launch(void* const* d_in, const int* in_sizes, int n_in,
                              void* d_out, int out_size) {
    const float* x  = (const float*)d_in[0];
    const int*   ix = (const int*)d_in[1];
    const float* Wf = (const float*)d_in[2];
    const float* bf = (const float*)d_in[3];
    const float* Wg = (const float*)d_in[4];
    const float* bg = (const float*)d_in[5];
    const float* Wh = (const float*)d_in[6];
    const float* bh = (const float*)d_in[7];
    float* out = (float*)d_out;
    (void)in_sizes; (void)n_in; (void)out_size;

    cudaFuncSetAttribute(k_tgz, cudaFuncAttributeMaxDynamicSharedMemorySize,
                         SMEM_TOTAL);

    k_prep1<<<PREP_CTAS, 1024>>>(ix);
    k_scan<<<1, S>>>();
    k_prep2<<<PREP_CTAS, 1024>>>();
    k_pass1<<<(B * S) / 8, 256>>>((const float4*)x, (const float4*)Wg, bg);

    k_bc<<<D / 256, 256>>>(Wh, bf, bh);
    k_wc<<<dim3(D / 32, D / 32), 256>>>(Wf, Wh);

    k_tgz<<<dim3((B * S) / 128, D / 128), 256, SMEM_TOTAL>>>((float4*)out);
}

// round 14
// speedup vs baseline: 1.0400x; 1.0279x over previous
#include <cuda_runtime.h>
#include <cuda_bf16.h>
#include <cstdint>

// Fixed problem shape (SoftAggBasic): x [B,N,D] f32, ix [N], S segments.
constexpr int B = 8;
constexpr int N = 65536;
constexpr int D = 512;
constexpr int S = 1024;
constexpr int PREP_CTAS = 4;
constexpr int ITEMS = N / (PREP_CTAS * 1024);  // 16

// HMMA GEMM tiling: z[8192,512] = X[8192,512] @ W[512,512]^T(n,k)
constexpr int KT = 32;              // K per SMEM stage
constexpr int NSTG = D / KT;        // 16 stages
constexpr int ROWB = 80;            // padded smem row: 32 bf16 = 64B + 16B pad
constexpr int A_SZ = 128 * ROWB;    // 10240 B per 128-row tile
constexpr int STG_AH = 0;
constexpr int STG_AL = A_SZ;
constexpr int STG_BH = 2 * A_SZ;
constexpr int STG_BL = 3 * A_SZ;
constexpr int STAGE = 4 * A_SZ;     // 40960 B
constexpr int SMEM_TOTAL = 2 * STAGE;  // 81920 B -> 2 CTAs/SM

// ---------------- device scratch (no allocations allowed) ----------------
__device__ int   g_ix[N];
__device__ int   g_hist4[PREP_CTAS][S];
__device__ int   g_offs[S + 1];
__device__ int   g_cursor[S];
__device__ int   g_perm[N];
__device__ __nv_bfloat16 g_xh[(size_t)B * S * D];   // xbar hi (8 MB)
__device__ __nv_bfloat16 g_xl[(size_t)B * S * D];   // xbar lo (8 MB)
__device__ __nv_bfloat16 g_WTh[(size_t)D * D];      // (Wf@Wh)^T hi  [n,k]
__device__ __nv_bfloat16 g_WTl[(size_t)D * D];      // (Wf@Wh)^T lo
__device__ float g_bc[D];                           // bf @ Wh + bh
__device__ float g_z[(size_t)B * S * D];            // 16 MB

// ---------------- helpers ----------------
__device__ __forceinline__ uint32_t smem_u32(const void* p) {
    uint32_t a;
    asm("{ .reg .u64 t; cvta.to.shared.u64 t, %1; cvt.u32.u64 %0, t; }"
        : "=r"(a) : "l"(p));
    return a;
}

__device__ __forceinline__ void cpa16(uint32_t dst, const void* src) {
    asm volatile("cp.async.cg.shared.global [%0], [%1], 16;"
                 :: "r"(dst), "l"(src) : "memory");
}
__device__ __forceinline__ void cpa_commit() {
    asm volatile("cp.async.commit_group;" ::: "memory");
}
template <int NW>
__device__ __forceinline__ void cpa_wait() {
    asm volatile("cp.async.wait_group %0;" :: "n"(NW) : "memory");
}

// split f32 -> bf16 hi/lo
__device__ __forceinline__ void bsplit(float v, unsigned short& h,
                                       unsigned short& l) {
    __nv_bfloat16 hb = __float2bfloat16_rn(v);
    __nv_bfloat16 lb = __float2bfloat16_rn(v - __bfloat162float(hb));
    h = __bfloat16_as_ushort(hb);
    l = __bfloat16_as_ushort(lb);
}

__device__ __forceinline__ void ldsm4(uint32_t& f0, uint32_t& f1, uint32_t& f2,
                                      uint32_t& f3, uint32_t addr) {
    asm volatile(
        "ldmatrix.sync.aligned.m8n8.x4.shared.b16 {%0,%1,%2,%3}, [%4];"
        : "=r"(f0), "=r"(f1), "=r"(f2), "=r"(f3) : "r"(addr));
}

__device__ __forceinline__ void hmma(float* d, const uint32_t* a,
                                     const uint32_t* b) {
    asm volatile(
        "mma.sync.aligned.m16n8k16.row.col.f32.bf16.bf16.f32 "
        "{%0,%1,%2,%3}, {%4,%5,%6,%7}, {%8,%9}, {%0,%1,%2,%3};"
        : "+f"(d[0]), "+f"(d[1]), "+f"(d[2]), "+f"(d[3])
        : "r"(a[0]), "r"(a[1]), "r"(a[2]), "r"(a[3]), "r"(b[0]), "r"(b[1]));
}

// ---------------- prep 1: ix normalize + per-CTA histogram ----------------
// int64/int32 autodetect: little-endian int64 in [0,1024) => odd words zero.
__global__ __launch_bounds__(1024) void k_prep1(const int* __restrict__ raw) {
    __shared__ int hist[S];
    int t = threadIdx.x, c = blockIdx.x;
    hist[t] = 0;
    int any = 0;
#pragma unroll
    for (int i = 0; i < 16; i++) any |= raw[2 * i + 1];
    __syncthreads();
    int base = c * (ITEMS * 1024);
#pragma unroll
    for (int i = 0; i < ITEMS; i++) {
        int n = base + i * 1024 + t;
        int v = (any == 0) ? raw[2 * n] : raw[n];
        g_ix[n] = v;
        atomicAdd(&hist[v], 1);
    }
    __syncthreads();
    g_hist4[c][t] = hist[t];
}

// single block, S=1024 threads, warp-shfl hierarchical scan
__global__ void k_scan() {
    __shared__ int ws[32];
    int t = threadIdx.x, lane = t & 31, w = t >> 5;
    int c = 0;
#pragma unroll
    for (int j = 0; j < PREP_CTAS; j++) c += g_hist4[j][t];
    int v = c;
#pragma unroll
    for (int off = 1; off < 32; off <<= 1) {
        int u = __shfl_up_sync(~0u, v, off);
        if (lane >= off) v += u;
    }
    if (lane == 31) ws[w] = v;
    __syncthreads();
    if (w == 0) {
        int s2 = ws[lane];
#pragma unroll
        for (int off = 1; off < 32; off <<= 1) {
            int u = __shfl_up_sync(~0u, s2, off);
            if (lane >= off) s2 += u;
        }
        ws[lane] = s2;
    }
    __syncthreads();
    int incl = v + (w ? ws[w - 1] : 0);
    g_offs[t + 1] = incl;
    if (t == 0) g_offs[0] = 0;
    g_cursor[t] = incl - c;
}

// ---------------- prep 2: scatter with smem-aggregated reservation -------
__global__ __launch_bounds__(1024) void k_prep2() {
    __shared__ int hist[S];
    __shared__ int basearr[S];
    int t = threadIdx.x, c = blockIdx.x;
    hist[t] = 0;
    __syncthreads();
    int base = c * (ITEMS * 1024);
    int lp[ITEMS], sv[ITEMS];
#pragma unroll
    for (int i = 0; i < ITEMS; i++) {
        int n = base + i * 1024 + t;
        int s = g_ix[n];
        sv[i] = s;
        lp[i] = atomicAdd(&hist[s], 1);
    }
    __syncthreads();
    basearr[t] = atomicAdd(&g_cursor[t], hist[t]);
    __syncthreads();
#pragma unroll
    for (int i = 0; i < ITEMS; i++)
        g_perm[basearr[sv[i]] + lp[i]] = base + i * 1024 + t;
}

// ---------------- pass 1: fused logits + softmax + weighted segment mean ---
// Warp per (b, segment); epilogue writes xbar as bf16 hi/lo split.
__global__ __launch_bounds__(256) void k_pass1(const float4* __restrict__ x4,
                                               const float4* __restrict__ Wg4,
                                               const float* __restrict__ bg) {
    int wid = threadIdx.x >> 5, lane = threadIdx.x & 31;
    int pair = blockIdx.x * 8 + wid;   // = b*S + s
    int b = pair >> 10;
    int s = pair & (S - 1);

    float4 wgv[4];
#pragma unroll
    for (int j = 0; j < 4; j++) wgv[j] = Wg4[lane + 32 * j];
    float bg0 = bg[0];

    int start = g_offs[s], end = g_offs[s + 1];
    const float4* xb = x4 + (size_t)b * N * (D / 4);

    float4 acc[4];
#pragma unroll
    for (int j = 0; j < 4; j++) acc[j] = make_float4(0.f, 0.f, 0.f, 0.f);
    float denom = 0.f;

    for (int r = start; r < end; r += 2) {
        int n0 = g_perm[r];
        int n1 = (r + 1 < end) ? g_perm[r + 1] : n0;
        const float4* p0 = xb + (size_t)n0 * (D / 4);
        const float4* p1 = xb + (size_t)n1 * (D / 4);
        float4 xv0[4], xv1[4];
#pragma unroll
        for (int j = 0; j < 4; j++) xv0[j] = p0[lane + 32 * j];
#pragma unroll
        for (int j = 0; j < 4; j++) xv1[j] = p1[lane + 32 * j];

        float d0 = 0.f, d1 = 0.f;
#pragma unroll
        for (int j = 0; j < 4; j++) {
            d0 += xv0[j].x * wgv[j].x + xv0[j].y * wgv[j].y +
                  xv0[j].z * wgv[j].z + xv0[j].w * wgv[j].w;
            d1 += xv1[j].x * wgv[j].x + xv1[j].y * wgv[j].y +
                  xv1[j].z * wgv[j].z + xv1[j].w * wgv[j].w;
        }
#pragma unroll
        for (int off = 16; off; off >>= 1) {
            d0 += __shfl_xor_sync(~0u, d0, off);
            d1 += __shfl_xor_sync(~0u, d1, off);
        }
        float e0 = expf(d0 + bg0);
        float e1 = (r + 1 < end) ? expf(d1 + bg0) : 0.f;
        denom += e0 + e1;
#pragma unroll
        for (int j = 0; j < 4; j++) {
            acc[j].x += e0 * xv0[j].x + e1 * xv1[j].x;
            acc[j].y += e0 * xv0[j].y + e1 * xv1[j].y;
            acc[j].z += e0 * xv0[j].z + e1 * xv1[j].z;
            acc[j].w += e0 * xv0[j].w + e1 * xv1[j].w;
        }
    }
    float inv = (denom > 0.f) ? 1.f / denom : 0.f;
#pragma unroll
    for (int j = 0; j < 4; j++) {
        float v0 = acc[j].x * inv, v1 = acc[j].y * inv;
        float v2 = acc[j].z * inv, v3 = acc[j].w * inv;
        unsigned short h0, h1, h2, h3, l0, l1, l2, l3;
        bsplit(v0, h0, l0);
        bsplit(v1, h1, l1);
        bsplit(v2, h2, l2);
        bsplit(v3, h3, l3);
        size_t off = (size_t)pair * D + 4 * (lane + 32 * j);
        uint2 uh, ul;
        uh.x = (uint32_t)h0 | ((uint32_t)h1 << 16);
        uh.y = (uint32_t)h2 | ((uint32_t)h3 << 16);
        ul.x = (uint32_t)l0 | ((uint32_t)l1 << 16);
        ul.y = (uint32_t)l2 | ((uint32_t)l3 << 16);
        *(uint2*)(g_xh + off) = uh;
        *(uint2*)(g_xl + off) = ul;
    }
}

// ---------------- fold weights: WcT = (Wf @ Wh)^T as bf16 hi/lo -----------
__global__ void k_bc(const float* __restrict__ Wh, const float* __restrict__ bf,
                     const float* __restrict__ bh) {
    int d = blockIdx.x * blockDim.x + threadIdx.x;
    float acc = bh[d];
    for (int k = 0; k < D; k++) acc += bf[k] * Wh[(size_t)k * D + d];
    g_bc[d] = acc;
}

__global__ __launch_bounds__(256) void k_wc(const float* __restrict__ Wf,
                                            const float* __restrict__ Wh) {
    __shared__ float Af[32][33], Bf[32][33];
    int t = threadIdx.x;
    int row0 = blockIdx.y * 32, col0 = blockIdx.x * 32;
    int c = t & 31, g = t >> 5;
    float acc[4] = {0.f, 0.f, 0.f, 0.f};
    for (int k0 = 0; k0 < D; k0 += 32) {
#pragma unroll
        for (int i = 0; i < 4; i++) {
            int idx = t + i * 256;
            int r = idx >> 5, cc = idx & 31;
            Af[r][cc] = Wf[(size_t)(row0 + r) * D + k0 + cc];
            Bf[r][cc] = Wh[(size_t)(k0 + r) * D + col0 + cc];
        }
        __syncthreads();
#pragma unroll
        for (int k = 0; k < 32; k++) {
            float bv = Bf[k][c];
#pragma unroll
            for (int i = 0; i < 4; i++) acc[i] += Af[g * 4 + i][k] * bv;
        }
        __syncthreads();
    }
    // transpose on write: WT[n][k] = Wc[k][n], split bf16 hi/lo
#pragma unroll
    for (int i = 0; i < 4; i++) {
        unsigned short h, l;
        bsplit(acc[i], h, l);
        size_t o = (size_t)(col0 + c) * D + row0 + g * 4 + i;
        g_WTh[o] = __ushort_as_bfloat16(h);
        g_WTl[o] = __ushort_as_bfloat16(l);
    }
}

// ---------------- HMMA GEMM: z = X @ WT^T + bc (bf16 hi/lo 3-term) --------
// CTA tile 128x128, 256 threads = 8 warps as 2(M)x4(N), warp tile 64x32.
// cp.async double-buffered K=32 stages (round-11-validated schedule).
// __launch_bounds__(256,2): regs capped at 128 -> 2 CTAs/SM -> all 256 CTAs
// in ONE wave (was 1.73 ragged waves at 1 CTA/SM) and 16 warps/SM to hide
// ldsm + sync latency.
__global__ __launch_bounds__(256, 2) void k_tgemm() {
    extern __shared__ char sm[];
    uint32_t sb = smem_u32(sm);
    int t = threadIdx.x;
    int lane = t & 31, wid = t >> 5;
    int m0 = blockIdx.x * 128, n0 = blockIdx.y * 128;
    int wm = (wid & 1) * 64;   // warp M offset in tile
    int wn = (wid >> 1) * 32;  // warp N offset in tile

    // loader role: thread t covers row t>>1, half (t&1) (16 bf16 = 32 B)
    int lrow = t >> 1, half = t & 1;
    const uint4* gah = (const uint4*)(g_xh + (size_t)(m0 + lrow) * D) + half * 2;
    const uint4* gal = (const uint4*)(g_xl + (size_t)(m0 + lrow) * D) + half * 2;
    const uint4* gbh = (const uint4*)(g_WTh + (size_t)(n0 + lrow) * D) + half * 2;
    const uint4* gbl = (const uint4*)(g_WTl + (size_t)(n0 + lrow) * D) + half * 2;
    uint32_t sto = (uint32_t)lrow * ROWB + half * 32;

    float d[4][4][4];
#pragma unroll
    for (int mi = 0; mi < 4; mi++)
#pragma unroll
        for (int nj = 0; nj < 4; nj++)
#pragma unroll
            for (int q = 0; q < 4; q++) d[mi][nj][q] = 0.f;

    auto load_stage = [&](int s) {
        uint32_t bp = sb + (uint32_t)(s & 1) * STAGE;
        int ko = s * 4;  // 4 uint4 per 32-elem k chunk (2 per half)
        cpa16(bp + STG_AH + sto, gah + ko);
        cpa16(bp + STG_AH + sto + 16, gah + ko + 1);
        cpa16(bp + STG_AL + sto, gal + ko);
        cpa16(bp + STG_AL + sto + 16, gal + ko + 1);
        cpa16(bp + STG_BH + sto, gbh + ko);
        cpa16(bp + STG_BH + sto + 16, gbh + ko + 1);
        cpa16(bp + STG_BL + sto, gbl + ko);
        cpa16(bp + STG_BL + sto + 16, gbl + ko + 1);
        cpa_commit();
    };

    load_stage(0);

    // ldmatrix per-lane offsets (validated round-8 mapping)
    int r8 = lane & 7, grp = lane >> 3;
    uint32_t a_off = (uint32_t)(((grp & 1) * 8 + r8) * ROWB + ((grp >> 1) * 8) * 2);
    uint32_t b_off = (uint32_t)((((grp >> 1) * 8) + r8) * ROWB + ((grp & 1) * 8) * 2);

    for (int s = 0; s < NSTG; s++) {
        if (s < NSTG - 1) load_stage(s + 1);
        if (s < NSTG - 1) cpa_wait<1>(); else cpa_wait<0>();
        __syncthreads();  // stage s resident for all warps

        uint32_t bb = sb + (uint32_t)(s & 1) * STAGE;
#pragma unroll
        for (int kk = 0; kk < KT; kk += 16) {
            uint32_t bH[4][2], bL[4][2];
#pragma unroll
            for (int ni = 0; ni < 2; ni++) {
                uint32_t bd = bb + (uint32_t)((wn + ni * 16) * ROWB + kk * 2) + b_off;
                ldsm4(bH[2 * ni][0], bH[2 * ni][1], bH[2 * ni + 1][0],
                      bH[2 * ni + 1][1], bd + STG_BH);
                ldsm4(bL[2 * ni][0], bL[2 * ni][1], bL[2 * ni + 1][0],
                      bL[2 * ni + 1][1], bd + STG_BL);
            }
#pragma unroll
            for (int mi = 0; mi < 4; mi++) {
                uint32_t aH[4], aL[4];
                uint32_t ad = bb + (uint32_t)((wm + mi * 16) * ROWB + kk * 2) + a_off;
                ldsm4(aH[0], aH[1], aH[2], aH[3], ad + STG_AH);
                ldsm4(aL[0], aL[1], aL[2], aL[3], ad + STG_AL);
#pragma unroll
                for (int nj = 0; nj < 4; nj++) {
                    hmma(d[mi][nj], aH, bH[nj]);
                    hmma(d[mi][nj], aH, bL[nj]);
                    hmma(d[mi][nj], aL, bH[nj]);
                }
            }
        }
        __syncthreads();  // all warps done with stage s before it is reloaded
    }

    // epilogue: fragment (row = lane>>2 [+8], col = 2*(lane&3) [+0,1]) + bias
    int fr = lane >> 2, fc = 2 * (lane & 3);
#pragma unroll
    for (int nj = 0; nj < 4; nj++) {
        int col = n0 + wn + nj * 8 + fc;
        float2 bb2 = *(const float2*)(g_bc + col);
#pragma unroll
        for (int mi = 0; mi < 4; mi++) {
            int row = m0 + wm + mi * 16 + fr;
            float2 o0, o1;
            o0.x = d[mi][nj][0] + bb2.x;
            o0.y = d[mi][nj][1] + bb2.y;
            o1.x = d[mi][nj][2] + bb2.x;
            o1.y = d[mi][nj][3] + bb2.y;
            *(float2*)(g_z + (size_t)row * D + col) = o0;
            *(float2*)(g_z + (size_t)(row + 8) * D + col) = o1;
        }
    }
}

// ---------------- gather/expand: out[b,n,:] = z[b, ix[n], :] ----------------
// Warp-per-row; z (16 MB) stays L2-resident; out written with streaming hint.
__global__ __launch_bounds__(256) void k_gather(float4* __restrict__ out4) {
    int wid = threadIdx.x >> 5, lane = threadIdx.x & 31;
    size_t row = (size_t)blockIdx.x * 8 + wid;  // b*N + n
    int n = (int)(row & (size_t)(N - 1));
    int b = (int)(row >> 16);  // N = 65536
    int s = g_ix[n];
    const float4* zp = (const float4*)g_z + ((size_t)(b * S + s)) * (D / 4);
    float4* op = out4 + row * (D / 4);
#pragma unroll
    for (int j = 0; j < 4; j++) {
        float4 v = zp[lane + 32 * j];
        __stcs(op + lane + 32 * j, v);
    }
}

// ---------------- launch ----------------
extern "C" void kernel_launch(void* const* d_in, const int* in_sizes, int n_in,
                              void* d_out, int out_size) {
    const float* x  = (const float*)d_in[0];
    const int*   ix = (const int*)d_in[1];
    const float* Wf = (const float*)d_in[2];
    const float* bf = (const float*)d_in[3];
    const float* Wg = (const float*)d_in[4];
    const float* bg = (const float*)d_in[5];
    const float* Wh = (const float*)d_in[6];
    const float* bh = (const float*)d_in[7];
    float* out = (float*)d_out;
    (void)in_sizes; (void)n_in; (void)out_size;

    cudaFuncSetAttribute(k_tgemm, cudaFuncAttributeMaxDynamicSharedMemorySize,
                         SMEM_TOTAL);

    k_prep1<<<PREP_CTAS, 1024>>>(ix);
    k_scan<<<1, S>>>();
    k_prep2<<<PREP_CTAS, 1024>>>();
    k_pass1<<<(B * S) / 8, 256>>>((const float4*)x, (const float4*)Wg, bg);

    k_bc<<<D / 256, 256>>>(Wh, bf, bh);
    k_wc<<<dim3(D / 32, D / 32), 256>>>(Wf, Wh);

    k_tgemm<<<dim3((B * S) / 128, D / 128), 256, SMEM_TOTAL>>>();

    k_gather<<<(B * N) / 8, 256>>>((float4*)out);
}

// round 15
// speedup vs baseline: 1.1863x; 1.1407x over previous
#include <cuda_runtime.h>
#include <cuda_bf16.h>
#include <cstdint>

// Fixed problem shape (SoftAggBasic): x [B,N,D] f32, ix [N], S segments.
constexpr int B = 8;
constexpr int N = 65536;
constexpr int D = 512;
constexpr int S = 1024;
constexpr int PREP_CTAS = 4;
constexpr int ITEMS = N / (PREP_CTAS * 1024);  // 16

// HMMA GEMM tiling: z[8192,512] = X[8192,512] @ W[512,512]^T(n,k)
constexpr int KT = 32;              // K per SMEM stage
constexpr int NSTG = D / KT;        // 16 stages
constexpr int ROWB = 80;            // padded smem row: 32 bf16 = 64B + 16B pad
constexpr int A_SZ = 128 * ROWB;    // 10240 B per 128-row tile
constexpr int STG_AH = 0;
constexpr int STG_AL = A_SZ;
constexpr int STG_BH = 2 * A_SZ;
constexpr int STG_BL = 3 * A_SZ;
constexpr int STAGE = 4 * A_SZ;     // 40960 B
constexpr int SMEM_TOTAL = 2 * STAGE;  // 81920 B -> 2 CTAs/SM

// ---------------- device scratch (no allocations allowed) ----------------
__device__ int   g_ix[N];
__device__ int   g_hist4[PREP_CTAS][S];
__device__ int   g_offs[S + 1];
__device__ int   g_cursor[S];
__device__ int   g_perm[N];
__device__ __nv_bfloat16 g_xh[(size_t)B * S * D];   // xbar hi (8 MB)
__device__ __nv_bfloat16 g_xl[(size_t)B * S * D];   // xbar lo (8 MB)
__device__ __nv_bfloat16 g_WTh[(size_t)D * D];      // (Wf@Wh)^T hi  [n,k]
__device__ __nv_bfloat16 g_WTl[(size_t)D * D];      // (Wf@Wh)^T lo
__device__ float g_bc[D];                           // bf @ Wh + bh
__device__ float g_z[(size_t)B * S * D];            // 16 MB

// ---------------- helpers ----------------
__device__ __forceinline__ uint32_t smem_u32(const void* p) {
    uint32_t a;
    asm("{ .reg .u64 t; cvta.to.shared.u64 t, %1; cvt.u32.u64 %0, t; }"
        : "=r"(a) : "l"(p));
    return a;
}

__device__ __forceinline__ void cpa16(uint32_t dst, const void* src) {
    asm volatile("cp.async.cg.shared.global [%0], [%1], 16;"
                 :: "r"(dst), "l"(src) : "memory");
}
__device__ __forceinline__ void cpa_commit() {
    asm volatile("cp.async.commit_group;" ::: "memory");
}
template <int NW>
__device__ __forceinline__ void cpa_wait() {
    asm volatile("cp.async.wait_group %0;" :: "n"(NW) : "memory");
}

// split f32 -> bf16 hi/lo
__device__ __forceinline__ void bsplit(float v, unsigned short& h,
                                       unsigned short& l) {
    __nv_bfloat16 hb = __float2bfloat16_rn(v);
    __nv_bfloat16 lb = __float2bfloat16_rn(v - __bfloat162float(hb));
    h = __bfloat16_as_ushort(hb);
    l = __bfloat16_as_ushort(lb);
}

__device__ __forceinline__ void ldsm4(uint32_t& f0, uint32_t& f1, uint32_t& f2,
                                      uint32_t& f3, uint32_t addr) {
    asm volatile(
        "ldmatrix.sync.aligned.m8n8.x4.shared.b16 {%0,%1,%2,%3}, [%4];"
        : "=r"(f0), "=r"(f1), "=r"(f2), "=r"(f3) : "r"(addr));
}

__device__ __forceinline__ void hmma(float* d, const uint32_t* a,
                                     const uint32_t* b) {
    asm volatile(
        "mma.sync.aligned.m16n8k16.row.col.f32.bf16.bf16.f32 "
        "{%0,%1,%2,%3}, {%4,%5,%6,%7}, {%8,%9}, {%0,%1,%2,%3};"
        : "+f"(d[0]), "+f"(d[1]), "+f"(d[2]), "+f"(d[3])
        : "r"(a[0]), "r"(a[1]), "r"(a[2]), "r"(a[3]), "r"(b[0]), "r"(b[1]));
}

// ---------------- prep 1: ix normalize + per-CTA histogram ----------------
// int64/int32 autodetect: little-endian int64 in [0,1024) => odd words zero.
__global__ __launch_bounds__(1024) void k_prep1(const int* __restrict__ raw) {
    __shared__ int hist[S];
    int t = threadIdx.x, c = blockIdx.x;
    hist[t] = 0;
    int any = 0;
#pragma unroll
    for (int i = 0; i < 16; i++) any |= raw[2 * i + 1];
    __syncthreads();
    int base = c * (ITEMS * 1024);
#pragma unroll
    for (int i = 0; i < ITEMS; i++) {
        int n = base + i * 1024 + t;
        int v = (any == 0) ? raw[2 * n] : raw[n];
        g_ix[n] = v;
        atomicAdd(&hist[v], 1);
    }
    __syncthreads();
    g_hist4[c][t] = hist[t];
}

// single block, S=1024 threads, warp-shfl hierarchical scan
__global__ void k_scan() {
    __shared__ int ws[32];
    int t = threadIdx.x, lane = t & 31, w = t >> 5;
    int c = 0;
#pragma unroll
    for (int j = 0; j < PREP_CTAS; j++) c += g_hist4[j][t];
    int v = c;
#pragma unroll
    for (int off = 1; off < 32; off <<= 1) {
        int u = __shfl_up_sync(~0u, v, off);
        if (lane >= off) v += u;
    }
    if (lane == 31) ws[w] = v;
    __syncthreads();
    if (w == 0) {
        int s2 = ws[lane];
#pragma unroll
        for (int off = 1; off < 32; off <<= 1) {
            int u = __shfl_up_sync(~0u, s2, off);
            if (lane >= off) s2 += u;
        }
        ws[lane] = s2;
    }
    __syncthreads();
    int incl = v + (w ? ws[w - 1] : 0);
    g_offs[t + 1] = incl;
    if (t == 0) g_offs[0] = 0;
    g_cursor[t] = incl - c;
}

// ---------------- prep 2: scatter with smem-aggregated reservation -------
__global__ __launch_bounds__(1024) void k_prep2() {
    __shared__ int hist[S];
    __shared__ int basearr[S];
    int t = threadIdx.x, c = blockIdx.x;
    hist[t] = 0;
    __syncthreads();
    int base = c * (ITEMS * 1024);
    int lp[ITEMS], sv[ITEMS];
#pragma unroll
    for (int i = 0; i < ITEMS; i++) {
        int n = base + i * 1024 + t;
        int s = g_ix[n];
        sv[i] = s;
        lp[i] = atomicAdd(&hist[s], 1);
    }
    __syncthreads();
    basearr[t] = atomicAdd(&g_cursor[t], hist[t]);
    __syncthreads();
#pragma unroll
    for (int i = 0; i < ITEMS; i++)
        g_perm[basearr[sv[i]] + lp[i]] = base + i * 1024 + t;
}

// ---------------- pass 1: fused logits + softmax + weighted segment mean ---
// Warp per (b, segment); epilogue writes xbar as bf16 hi/lo split.
__global__ __launch_bounds__(256) void k_pass1(const float4* __restrict__ x4,
                                               const float4* __restrict__ Wg4,
                                               const float* __restrict__ bg) {
    int wid = threadIdx.x >> 5, lane = threadIdx.x & 31;
    int pair = blockIdx.x * 8 + wid;   // = b*S + s
    int b = pair >> 10;
    int s = pair & (S - 1);

    float4 wgv[4];
#pragma unroll
    for (int j = 0; j < 4; j++) wgv[j] = Wg4[lane + 32 * j];
    float bg0 = bg[0];

    int start = g_offs[s], end = g_offs[s + 1];
    const float4* xb = x4 + (size_t)b * N * (D / 4);

    float4 acc[4];
#pragma unroll
    for (int j = 0; j < 4; j++) acc[j] = make_float4(0.f, 0.f, 0.f, 0.f);
    float denom = 0.f;

    for (int r = start; r < end; r += 2) {
        int n0 = g_perm[r];
        int n1 = (r + 1 < end) ? g_perm[r + 1] : n0;
        const float4* p0 = xb + (size_t)n0 * (D / 4);
        const float4* p1 = xb + (size_t)n1 * (D / 4);
        float4 xv0[4], xv1[4];
#pragma unroll
        for (int j = 0; j < 4; j++) xv0[j] = p0[lane + 32 * j];
#pragma unroll
        for (int j = 0; j < 4; j++) xv1[j] = p1[lane + 32 * j];

        float d0 = 0.f, d1 = 0.f;
#pragma unroll
        for (int j = 0; j < 4; j++) {
            d0 += xv0[j].x * wgv[j].x + xv0[j].y * wgv[j].y +
                  xv0[j].z * wgv[j].z + xv0[j].w * wgv[j].w;
            d1 += xv1[j].x * wgv[j].x + xv1[j].y * wgv[j].y +
                  xv1[j].z * wgv[j].z + xv1[j].w * wgv[j].w;
        }
#pragma unroll
        for (int off = 16; off; off >>= 1) {
            d0 += __shfl_xor_sync(~0u, d0, off);
            d1 += __shfl_xor_sync(~0u, d1, off);
        }
        float e0 = expf(d0 + bg0);
        float e1 = (r + 1 < end) ? expf(d1 + bg0) : 0.f;
        denom += e0 + e1;
#pragma unroll
        for (int j = 0; j < 4; j++) {
            acc[j].x += e0 * xv0[j].x + e1 * xv1[j].x;
            acc[j].y += e0 * xv0[j].y + e1 * xv1[j].y;
            acc[j].z += e0 * xv0[j].z + e1 * xv1[j].z;
            acc[j].w += e0 * xv0[j].w + e1 * xv1[j].w;
        }
    }
    float inv = (denom > 0.f) ? 1.f / denom : 0.f;
#pragma unroll
    for (int j = 0; j < 4; j++) {
        float v0 = acc[j].x * inv, v1 = acc[j].y * inv;
        float v2 = acc[j].z * inv, v3 = acc[j].w * inv;
        unsigned short h0, h1, h2, h3, l0, l1, l2, l3;
        bsplit(v0, h0, l0);
        bsplit(v1, h1, l1);
        bsplit(v2, h2, l2);
        bsplit(v3, h3, l3);
        size_t off = (size_t)pair * D + 4 * (lane + 32 * j);
        uint2 uh, ul;
        uh.x = (uint32_t)h0 | ((uint32_t)h1 << 16);
        uh.y = (uint32_t)h2 | ((uint32_t)h3 << 16);
        ul.x = (uint32_t)l0 | ((uint32_t)l1 << 16);
        ul.y = (uint32_t)l2 | ((uint32_t)l3 << 16);
        *(uint2*)(g_xh + off) = uh;
        *(uint2*)(g_xl + off) = ul;
    }
}

// ---------------- fold weights: WcT = (Wf @ Wh)^T as bf16 hi/lo -----------
__global__ void k_bc(const float* __restrict__ Wh, const float* __restrict__ bf,
                     const float* __restrict__ bh) {
    int d = blockIdx.x * blockDim.x + threadIdx.x;
    float acc = bh[d];
    for (int k = 0; k < D; k++) acc += bf[k] * Wh[(size_t)k * D + d];
    g_bc[d] = acc;
}

__global__ __launch_bounds__(256) void k_wc(const float* __restrict__ Wf,
                                            const float* __restrict__ Wh) {
    __shared__ float Af[32][33], Bf[32][33];
    int t = threadIdx.x;
    int row0 = blockIdx.y * 32, col0 = blockIdx.x * 32;
    int c = t & 31, g = t >> 5;
    float acc[4] = {0.f, 0.f, 0.f, 0.f};
    for (int k0 = 0; k0 < D; k0 += 32) {
#pragma unroll
        for (int i = 0; i < 4; i++) {
            int idx = t + i * 256;
            int r = idx >> 5, cc = idx & 31;
            Af[r][cc] = Wf[(size_t)(row0 + r) * D + k0 + cc];
            Bf[r][cc] = Wh[(size_t)(k0 + r) * D + col0 + cc];
        }
        __syncthreads();
#pragma unroll
        for (int k = 0; k < 32; k++) {
            float bv = Bf[k][c];
#pragma unroll
            for (int i = 0; i < 4; i++) acc[i] += Af[g * 4 + i][k] * bv;
        }
        __syncthreads();
    }
    // transpose on write: WT[n][k] = Wc[k][n], split bf16 hi/lo
#pragma unroll
    for (int i = 0; i < 4; i++) {
        unsigned short h, l;
        bsplit(acc[i], h, l);
        size_t o = (size_t)(col0 + c) * D + row0 + g * 4 + i;
        g_WTh[o] = __ushort_as_bfloat16(h);
        g_WTl[o] = __ushort_as_bfloat16(l);
    }
}

// ---------------- HMMA GEMM: z = X @ WT^T + bc (bf16 hi/lo 3-term) --------
// CTA tile 128x128, 256 threads = 8 warps as 2(M)x4(N), warp tile 64x32.
// cp.async double-buffered K=32 stages. A-fragment ldsm SOFTWARE-PIPELINED:
// frags for mi+1 are issued before mi's 12 HMMAs, so the ldsm->hmma RAW
// latency (~30cyc) hides behind compute instead of being exposed 8x/stage.
// __launch_bounds__(256,2): 2 CTAs/SM, one full wave.
__global__ __launch_bounds__(256, 2) void k_tgemm() {
    extern __shared__ char sm[];
    uint32_t sb = smem_u32(sm);
    int t = threadIdx.x;
    int lane = t & 31, wid = t >> 5;
    int m0 = blockIdx.x * 128, n0 = blockIdx.y * 128;
    int wm = (wid & 1) * 64;   // warp M offset in tile
    int wn = (wid >> 1) * 32;  // warp N offset in tile

    // loader role: thread t covers row t>>1, half (t&1) (16 bf16 = 32 B)
    int lrow = t >> 1, half = t & 1;
    const uint4* gah = (const uint4*)(g_xh + (size_t)(m0 + lrow) * D) + half * 2;
    const uint4* gal = (const uint4*)(g_xl + (size_t)(m0 + lrow) * D) + half * 2;
    const uint4* gbh = (const uint4*)(g_WTh + (size_t)(n0 + lrow) * D) + half * 2;
    const uint4* gbl = (const uint4*)(g_WTl + (size_t)(n0 + lrow) * D) + half * 2;
    uint32_t sto = (uint32_t)lrow * ROWB + half * 32;

    float d[4][4][4];
#pragma unroll
    for (int mi = 0; mi < 4; mi++)
#pragma unroll
        for (int nj = 0; nj < 4; nj++)
#pragma unroll
            for (int q = 0; q < 4; q++) d[mi][nj][q] = 0.f;

    auto load_stage = [&](int s) {
        uint32_t bp = sb + (uint32_t)(s & 1) * STAGE;
        int ko = s * 4;  // 4 uint4 per 32-elem k chunk (2 per half)
        cpa16(bp + STG_AH + sto, gah + ko);
        cpa16(bp + STG_AH + sto + 16, gah + ko + 1);
        cpa16(bp + STG_AL + sto, gal + ko);
        cpa16(bp + STG_AL + sto + 16, gal + ko + 1);
        cpa16(bp + STG_BH + sto, gbh + ko);
        cpa16(bp + STG_BH + sto + 16, gbh + ko + 1);
        cpa16(bp + STG_BL + sto, gbl + ko);
        cpa16(bp + STG_BL + sto + 16, gbl + ko + 1);
        cpa_commit();
    };

    load_stage(0);

    // ldmatrix per-lane offsets (validated round-8 mapping)
    int r8 = lane & 7, grp = lane >> 3;
    uint32_t a_off = (uint32_t)(((grp & 1) * 8 + r8) * ROWB + ((grp >> 1) * 8) * 2);
    uint32_t b_off = (uint32_t)((((grp >> 1) * 8) + r8) * ROWB + ((grp & 1) * 8) * 2);

    for (int s = 0; s < NSTG; s++) {
        if (s < NSTG - 1) load_stage(s + 1);
        if (s < NSTG - 1) cpa_wait<1>(); else cpa_wait<0>();
        __syncthreads();  // stage s resident for all warps

        uint32_t bb = sb + (uint32_t)(s & 1) * STAGE;
#pragma unroll
        for (int kk = 0; kk < KT; kk += 16) {
            uint32_t bH[4][2], bL[4][2];
#pragma unroll
            for (int ni = 0; ni < 2; ni++) {
                uint32_t bd = bb + (uint32_t)((wn + ni * 16) * ROWB + kk * 2) + b_off;
                ldsm4(bH[2 * ni][0], bH[2 * ni][1], bH[2 * ni + 1][0],
                      bH[2 * ni + 1][1], bd + STG_BH);
                ldsm4(bL[2 * ni][0], bL[2 * ni][1], bL[2 * ni + 1][0],
                      bL[2 * ni + 1][1], bd + STG_BL);
            }
            // prologue: A frags for mi=0
            uint32_t aHc[4], aLc[4];
            {
                uint32_t ad = bb + (uint32_t)(wm * ROWB + kk * 2) + a_off;
                ldsm4(aHc[0], aHc[1], aHc[2], aHc[3], ad + STG_AH);
                ldsm4(aLc[0], aLc[1], aLc[2], aLc[3], ad + STG_AL);
            }
#pragma unroll
            for (int mi = 0; mi < 4; mi++) {
                uint32_t aHn[4], aLn[4];
                if (mi < 3) {  // prefetch next mi's fragments BEFORE compute
                    uint32_t ad = bb +
                        (uint32_t)((wm + (mi + 1) * 16) * ROWB + kk * 2) + a_off;
                    ldsm4(aHn[0], aHn[1], aHn[2], aHn[3], ad + STG_AH);
                    ldsm4(aLn[0], aLn[1], aLn[2], aLn[3], ad + STG_AL);
                }
#pragma unroll
                for (int nj = 0; nj < 4; nj++) {
                    hmma(d[mi][nj], aHc, bH[nj]);
                    hmma(d[mi][nj], aHc, bL[nj]);
                    hmma(d[mi][nj], aLc, bH[nj]);
                }
                if (mi < 3) {
#pragma unroll
                    for (int q = 0; q < 4; q++) {
                        aHc[q] = aHn[q];
                        aLc[q] = aLn[q];
                    }
                }
            }
        }
        __syncthreads();  // all warps done with stage s before it is reloaded
    }

    // epilogue: fragment (row = lane>>2 [+8], col = 2*(lane&3) [+0,1]) + bias
    int fr = lane >> 2, fc = 2 * (lane & 3);
#pragma unroll
    for (int nj = 0; nj < 4; nj++) {
        int col = n0 + wn + nj * 8 + fc;
        float2 bb2 = *(const float2*)(g_bc + col);
#pragma unroll
        for (int mi = 0; mi < 4; mi++) {
            int row = m0 + wm + mi * 16 + fr;
            float2 o0, o1;
            o0.x = d[mi][nj][0] + bb2.x;
            o0.y = d[mi][nj][1] + bb2.y;
            o1.x = d[mi][nj][2] + bb2.x;
            o1.y = d[mi][nj][3] + bb2.y;
            *(float2*)(g_z + (size_t)row * D + col) = o0;
            *(float2*)(g_z + (size_t)(row + 8) * D + col) = o1;
        }
    }
}

// ---------------- gather/expand: out[b,n,:] = z[b, ix[n], :] ----------------
// Warp-per-row; z (16 MB) stays L2-resident; out written with streaming hint.
__global__ __launch_bounds__(256) void k_gather(float4* __restrict__ out4) {
    int wid = threadIdx.x >> 5, lane = threadIdx.x & 31;
    size_t row = (size_t)blockIdx.x * 8 + wid;  // b*N + n
    int n = (int)(row & (size_t)(N - 1));
    int b = (int)(row >> 16);  // N = 65536
    int s = g_ix[n];
    const float4* zp = (const float4*)g_z + ((size_t)(b * S + s)) * (D / 4);
    float4* op = out4 + row * (D / 4);
#pragma unroll
    for (int j = 0; j < 4; j++) {
        float4 v = zp[lane + 32 * j];
        __stcs(op + lane + 32 * j, v);
    }
}

// ---------------- launch ----------------
// bc/wc run on a side stream forked at entry so they overlap prep+pass1 in
// the captured graph. API issue order keeps pass1 as launch #4 (ncu slot).
extern "C" void kernel_launch(void* const* d_in, const int* in_sizes, int n_in,
                              void* d_out, int out_size) {
    const float* x  = (const float*)d_in[0];
    const int*   ix = (const int*)d_in[1];
    const float* Wf = (const float*)d_in[2];
    const float* bf = (const float*)d_in[3];
    const float* Wg = (const float*)d_in[4];
    const float* bg = (const float*)d_in[5];
    const float* Wh = (const float*)d_in[6];
    const float* bh = (const float*)d_in[7];
    float* out = (float*)d_out;
    (void)in_sizes; (void)n_in; (void)out_size;

    static cudaStream_t s2 = nullptr;
    static cudaEvent_t evFork = nullptr, evW = nullptr;
    if (s2 == nullptr) {
        cudaStreamCreateWithFlags(&s2, cudaStreamNonBlocking);
        cudaEventCreateWithFlags(&evFork, cudaEventDisableTiming);
        cudaEventCreateWithFlags(&evW, cudaEventDisableTiming);
        cudaFuncSetAttribute(k_tgemm,
                             cudaFuncAttributeMaxDynamicSharedMemorySize,
                             SMEM_TOTAL);
    }

    // fork point at entry (captured legacy stream)
    cudaEventRecord(evFork, 0);

    // main chain: prep + pass1 (pass1 = 4th launch -> ncu capture slot)
    k_prep1<<<PREP_CTAS, 1024>>>(ix);
    k_scan<<<1, S>>>();
    k_prep2<<<PREP_CTAS, 1024>>>();
    k_pass1<<<(B * S) / 8, 256>>>((const float4*)x, (const float4*)Wg, bg);

    // side chain: weight folding, concurrent with the main chain in-graph
    cudaStreamWaitEvent(s2, evFork, 0);
    k_bc<<<D / 256, 256, 0, s2>>>(Wh, bf, bh);
    k_wc<<<dim3(D / 32, D / 32), 256, 0, s2>>>(Wf, Wh);
    cudaEventRecord(evW, s2);

    // join: tgemm needs pass1 (main) + wc/bc (side)
    cudaStreamWaitEvent(0, evW, 0);
    k_tgemm<<<dim3((B * S) / 128, D / 128), 256, SMEM_TOTAL>>>();

    k_gather<<<(B * N) / 8, 256>>>((float4*)out);
}